// round 4
// baseline (speedup 1.0000x reference)
#include <cuda_runtime.h>
#include <cstdint>

// ---------------------------------------------------------------------------
// ParticleExplorer, time-parallel formulation.
// Per step: E <- E * Rz(pa) * Ry(na);  x <- x + sp * E.col0
// Decompose N=1024 steps into C=32 chunks of L=32:
//   K1 chunk_kernel: per (particle,chunk) compute chunk product P and local
//                    displacement d (in chunk-start frame).      [B*C threads]
//   K2 scan_kernel : per particle, serial scan over 32 chunks:
//                    record chunk-start (E,x); x+=E*d; E<-E*P; renorm.
//   K3 emit_kernel : per (particle,chunk) replay 32 steps from stored start,
//                    emit X via coalescing smem transpose; also write the
//                    speeds/pa/na pass-through copies + states zeros.
// Output: ts[N] | X[B][N][3] | states[B][N]=0 | speeds | pa | na
// ---------------------------------------------------------------------------

#define LCH 32
#define MAXBC (8192 * 32)

__device__ float g_P [9][MAXBC];   // chunk products (columns a,b,c)
__device__ float g_D [3][MAXBC];   // chunk local displacements
__device__ float g_SE[9][MAXBC];   // chunk-start frames
__device__ float g_SX[3][MAXBC];   // chunk-start positions

__device__ __forceinline__ void frame_step(float pa, float na,
    float& a0, float& a1, float& a2,
    float& b0, float& b1, float& b2,
    float& c0, float& c1, float& c2)
{
    float s1, cc1, s2, cc2;
    __sincosf(pa, &s1, &cc1);
    __sincosf(na, &s2, &cc2);
    float p00 = cc1 * cc2, p10 = s1 * cc2;
    float p02 = cc1 * s2,  p12 = s1 * s2;

    float na0 = fmaf(p00, a0, fmaf(p10, b0, -s2 * c0));
    float na1 = fmaf(p00, a1, fmaf(p10, b1, -s2 * c1));
    float na2 = fmaf(p00, a2, fmaf(p10, b2, -s2 * c2));
    float nb0 = fmaf(cc1, b0, -s1 * a0);
    float nb1 = fmaf(cc1, b1, -s1 * a1);
    float nb2 = fmaf(cc1, b2, -s1 * a2);
    float nc0 = fmaf(p02, a0, fmaf(p12, b0, cc2 * c0));
    float nc1 = fmaf(p02, a1, fmaf(p12, b1, cc2 * c1));
    float nc2 = fmaf(p02, a2, fmaf(p12, b2, cc2 * c2));
    a0 = na0; a1 = na1; a2 = na2;
    b0 = nb0; b1 = nb1; b2 = nb2;
    c0 = nc0; c1 = nc1; c2 = nc2;
}

// ---- K1: per-chunk product + local displacement -----------------------------
__global__ void __launch_bounds__(256)
chunk_kernel(const float* __restrict__ spd, const float* __restrict__ pan,
             const float* __restrict__ nanp, int B, int N, int C)
{
    int g = blockIdx.x * blockDim.x + threadIdx.x;
    if (g >= B * C) return;
    int p  = g / C;
    int ch = g - p * C;
    size_t base = (size_t)p * N + (size_t)ch * LCH;

    const float4* sp4 = (const float4*)(spd  + base);
    const float4* pa4 = (const float4*)(pan  + base);
    const float4* na4 = (const float4*)(nanp + base);

    float a0=1.f,a1=0.f,a2=0.f, b0=0.f,b1=1.f,b2=0.f, c0=0.f,c1=0.f,c2=1.f;
    float d0=0.f,d1=0.f,d2=0.f;

    #pragma unroll
    for (int q = 0; q < LCH / 4; q++) {
        float4 sp = sp4[q], pa = pa4[q], na = na4[q];
        frame_step(pa.x, na.x, a0,a1,a2,b0,b1,b2,c0,c1,c2);
        d0 = fmaf(sp.x, a0, d0); d1 = fmaf(sp.x, a1, d1); d2 = fmaf(sp.x, a2, d2);
        frame_step(pa.y, na.y, a0,a1,a2,b0,b1,b2,c0,c1,c2);
        d0 = fmaf(sp.y, a0, d0); d1 = fmaf(sp.y, a1, d1); d2 = fmaf(sp.y, a2, d2);
        frame_step(pa.z, na.z, a0,a1,a2,b0,b1,b2,c0,c1,c2);
        d0 = fmaf(sp.z, a0, d0); d1 = fmaf(sp.z, a1, d1); d2 = fmaf(sp.z, a2, d2);
        frame_step(pa.w, na.w, a0,a1,a2,b0,b1,b2,c0,c1,c2);
        d0 = fmaf(sp.w, a0, d0); d1 = fmaf(sp.w, a1, d1); d2 = fmaf(sp.w, a2, d2);
    }

    g_P[0][g]=a0; g_P[1][g]=a1; g_P[2][g]=a2;
    g_P[3][g]=b0; g_P[4][g]=b1; g_P[5][g]=b2;
    g_P[6][g]=c0; g_P[7][g]=c1; g_P[8][g]=c2;
    g_D[0][g]=d0; g_D[1][g]=d1; g_D[2][g]=d2;
}

// ---- K2: serial scan over chunks per particle (+ ts) ------------------------
__global__ void __launch_bounds__(256)
scan_kernel(const float* __restrict__ x0, const float* __restrict__ e0i,
            const float* __restrict__ e1i, const float* __restrict__ e2i,
            float* __restrict__ ts, const int* __restrict__ dtp,
            int B, int N, int C)
{
    int p = blockIdx.x * blockDim.x + threadIdx.x;

    if (p < N) {
        float dtf = 1.0f;
        if (dtp) {
            int v = dtp[0];
            if (v >= 1 && v <= 1000000) dtf = (float)v;
            else { float f = __int_as_float(v); if (f > 0.f && f < 1.0e6f) dtf = f; }
        }
        ts[p] = (float)p * dtf;
    }
    if (p >= B) return;

    float a0=e0i[p*3+0], a1=e0i[p*3+1], a2=e0i[p*3+2];
    float b0=e1i[p*3+0], b1=e1i[p*3+1], b2=e1i[p*3+2];
    float c0=e2i[p*3+0], c1=e2i[p*3+1], c2=e2i[p*3+2];
    float x =x0 [p*3+0], y =x0 [p*3+1], z =x0 [p*3+2];

    int g = p * C;
    for (int ch = 0; ch < C; ch++, g++) {
        g_SE[0][g]=a0; g_SE[1][g]=a1; g_SE[2][g]=a2;
        g_SE[3][g]=b0; g_SE[4][g]=b1; g_SE[5][g]=b2;
        g_SE[6][g]=c0; g_SE[7][g]=c1; g_SE[8][g]=c2;
        g_SX[0][g]=x;  g_SX[1][g]=y;  g_SX[2][g]=z;

        float d0=g_D[0][g], d1=g_D[1][g], d2=g_D[2][g];
        x = fmaf(d0,a0, fmaf(d1,b0, fmaf(d2,c0, x)));
        y = fmaf(d0,a1, fmaf(d1,b1, fmaf(d2,c1, y)));
        z = fmaf(d0,a2, fmaf(d1,b2, fmaf(d2,c2, z)));

        float q0=g_P[0][g],q1=g_P[1][g],q2=g_P[2][g];
        float q3=g_P[3][g],q4=g_P[4][g],q5=g_P[5][g];
        float q6=g_P[6][g],q7=g_P[7][g],q8=g_P[8][g];

        float na0=fmaf(q0,a0,fmaf(q1,b0,q2*c0));
        float na1=fmaf(q0,a1,fmaf(q1,b1,q2*c1));
        float na2=fmaf(q0,a2,fmaf(q1,b2,q2*c2));
        float nb0=fmaf(q3,a0,fmaf(q4,b0,q5*c0));
        float nb1=fmaf(q3,a1,fmaf(q4,b1,q5*c1));
        float nb2=fmaf(q3,a2,fmaf(q4,b2,q5*c2));
        float nc0=fmaf(q6,a0,fmaf(q7,b0,q8*c0));
        float nc1=fmaf(q6,a1,fmaf(q7,b1,q8*c1));
        float nc2=fmaf(q6,a2,fmaf(q7,b2,q8*c2));
        a0=na0;a1=na1;a2=na2; b0=nb0;b1=nb1;b2=nb2; c0=nc0;c1=nc1;c2=nc2;

        // Re-orthonormalize once per chunk (drift control).
        float inv = rsqrtf(fmaf(a0,a0, fmaf(a1,a1, a2*a2)));
        a0*=inv; a1*=inv; a2*=inv;
        float dd = fmaf(b0,a0, fmaf(b1,a1, b2*a2));
        b0 = fmaf(-dd,a0,b0); b1 = fmaf(-dd,a1,b1); b2 = fmaf(-dd,a2,b2);
        inv = rsqrtf(fmaf(b0,b0, fmaf(b1,b1, b2*b2)));
        b0*=inv; b1*=inv; b2*=inv;
        c0 = a1*b2 - a2*b1;
        c1 = a2*b0 - a0*b2;
        c2 = a0*b1 - a1*b0;
    }
}

// ---- K3: replay chunks, emit X (coalesced) + aux outputs --------------------
// Requires C == 32 (N == 1024). Block = 64 threads = 2 particles x 32 chunks.
__global__ void __launch_bounds__(64)
emit_kernel(const float* __restrict__ spd, const float* __restrict__ pan,
            const float* __restrict__ nanp,
            float* __restrict__ X, float* __restrict__ spo,
            float* __restrict__ pao, float* __restrict__ nao,
            float* __restrict__ states, int B, int N, int C)
{
    __shared__ float sX[2][32][99];   // pitch 99: gcd(3,32)=1 -> conflict-free

    int pp = threadIdx.x >> 5;
    int ch = threadIdx.x & 31;
    int p  = blockIdx.x * 2 + pp;
    int g  = p * C + ch;

    float a0=g_SE[0][g], a1=g_SE[1][g], a2=g_SE[2][g];
    float b0=g_SE[3][g], b1=g_SE[4][g], b2=g_SE[5][g];
    float c0=g_SE[6][g], c1=g_SE[7][g], c2=g_SE[8][g];
    float x =g_SX[0][g], y =g_SX[1][g], z =g_SX[2][g];

    size_t base = (size_t)p * N + (size_t)ch * LCH;
    const float4* sp4 = (const float4*)(spd  + base);
    const float4* pa4 = (const float4*)(pan  + base);
    const float4* na4 = (const float4*)(nanp + base);
    float4* spo4 = (float4*)(spo    + base);
    float4* pao4 = (float4*)(pao    + base);
    float4* nao4 = (float4*)(nao    + base);
    float4* st4  = (float4*)(states + base);
    const float4 zero4 = make_float4(0.f, 0.f, 0.f, 0.f);

    float* sxr = &sX[pp][ch][0];

    #pragma unroll 2
    for (int q = 0; q < LCH / 4; q++) {
        float4 sp = sp4[q], pa = pa4[q], na = na4[q];
        spo4[q] = sp; pao4[q] = pa; nao4[q] = na; st4[q] = zero4;
        int t = q * 4;

        frame_step(pa.x, na.x, a0,a1,a2,b0,b1,b2,c0,c1,c2);
        x = fmaf(sp.x,a0,x); y = fmaf(sp.x,a1,y); z = fmaf(sp.x,a2,z);
        sxr[t*3+0]=x; sxr[t*3+1]=y; sxr[t*3+2]=z;

        frame_step(pa.y, na.y, a0,a1,a2,b0,b1,b2,c0,c1,c2);
        x = fmaf(sp.y,a0,x); y = fmaf(sp.y,a1,y); z = fmaf(sp.y,a2,z);
        sxr[(t+1)*3+0]=x; sxr[(t+1)*3+1]=y; sxr[(t+1)*3+2]=z;

        frame_step(pa.z, na.z, a0,a1,a2,b0,b1,b2,c0,c1,c2);
        x = fmaf(sp.z,a0,x); y = fmaf(sp.z,a1,y); z = fmaf(sp.z,a2,z);
        sxr[(t+2)*3+0]=x; sxr[(t+2)*3+1]=y; sxr[(t+2)*3+2]=z;

        frame_step(pa.w, na.w, a0,a1,a2,b0,b1,b2,c0,c1,c2);
        x = fmaf(sp.w,a0,x); y = fmaf(sp.w,a1,y); z = fmaf(sp.w,a2,z);
        sxr[(t+3)*3+0]=x; sxr[(t+3)*3+1]=y; sxr[(t+3)*3+2]=z;
    }
    __syncthreads();

    // Flush: block's 2 particles hold full [N][3] rows; stores coalesced.
    const int per = 3 * N;  // 3072 = 32 chunks * 96
    size_t xb = (size_t)(blockIdx.x * 2) * per;
    for (int j = threadIdx.x; j < 2 * per; j += 64) {
        int ppi = (j >= per) ? 1 : 0;
        int jj  = j - ppi * per;
        int cc  = jj / 96;
        int off = jj - cc * 96;
        X[xb + j] = sX[ppi][cc][off];
    }
}

// ---------------------------------------------------------------------------
// Fallback (proven round-2 path) for unexpected shapes.
// ---------------------------------------------------------------------------
#define PPB 32
#define TT  32
#define SPITCH 33

__global__ void __launch_bounds__(PPB)
explorer_kernel(const float* __restrict__ x0, const float* __restrict__ e0i,
                const float* __restrict__ e1i, const float* __restrict__ e2i,
                const float* __restrict__ spd, const float* __restrict__ pan,
                const float* __restrict__ nan_, float* __restrict__ X,
                int B, int N)
{
    __shared__ float s_sp[TT][SPITCH];
    __shared__ float s_pa[TT][SPITCH];
    __shared__ float s_na[TT][SPITCH];
    __shared__ float s_X[3 * TT][SPITCH];

    const int lane  = threadIdx.x;
    const int pbase = blockIdx.x * PPB;
    const int p     = pbase + lane;
    const bool act  = (p < B);

    float a0=1.f,a1=0.f,a2=0.f, b0=0.f,b1=1.f,b2=0.f, c0=0.f,c1=0.f,c2=1.f;
    float x=0.f, y=0.f, z=0.f;
    if (act) {
        a0=e0i[p*3+0]; a1=e0i[p*3+1]; a2=e0i[p*3+2];
        b0=e1i[p*3+0]; b1=e1i[p*3+1]; b2=e1i[p*3+2];
        c0=e2i[p*3+0]; c1=e2i[p*3+1]; c2=e2i[p*3+2];
        x =x0 [p*3+0]; y =x0 [p*3+1]; z =x0 [p*3+2];
    }

    for (int t0 = 0; t0 < N; t0 += TT) {
        #pragma unroll
        for (int k = 0; k < PPB; k++) {
            int gp = pbase + k;
            float vs=0.f, vp=0.f, vn=0.f;
            if (gp < B && t0 + lane < N) {
                size_t gidx = (size_t)gp * N + (size_t)t0 + lane;
                vs = spd[gidx]; vp = pan[gidx]; vn = nan_[gidx];
            }
            s_sp[lane][k]=vs; s_pa[lane][k]=vp; s_na[lane][k]=vn;
        }
        __syncthreads();

        if (act) {
            int nt = (N - t0 < TT) ? (N - t0) : TT;
            for (int tt = 0; tt < nt; tt++) {
                frame_step(s_pa[tt][lane], s_na[tt][lane],
                           a0,a1,a2,b0,b1,b2,c0,c1,c2);
                float s = s_sp[tt][lane];
                x = fmaf(s,a0,x); y = fmaf(s,a1,y); z = fmaf(s,a2,z);
                s_X[3*tt+0][lane]=x; s_X[3*tt+1][lane]=y; s_X[3*tt+2][lane]=z;
            }
            float inv = rsqrtf(fmaf(a0,a0, fmaf(a1,a1, a2*a2)));
            a0*=inv; a1*=inv; a2*=inv;
            float d = fmaf(b0,a0, fmaf(b1,a1, b2*a2));
            b0=fmaf(-d,a0,b0); b1=fmaf(-d,a1,b1); b2=fmaf(-d,a2,b2);
            inv = rsqrtf(fmaf(b0,b0, fmaf(b1,b1, b2*b2)));
            b0*=inv; b1*=inv; b2*=inv;
            c0=a1*b2-a2*b1; c1=a2*b0-a0*b2; c2=a0*b1-a1*b0;
        }
        __syncthreads();

        #pragma unroll
        for (int k = 0; k < PPB; k++) {
            int gp = pbase + k;
            if (gp < B) {
                size_t bidx = (size_t)gp*3*N + (size_t)t0*3;
                #pragma unroll
                for (int chn = 0; chn < 3; chn++)
                    if (t0*3 + chn*32 + lane < 3*N)
                        X[bidx + chn*32 + lane] = s_X[chn*32 + lane][k];
            }
        }
    }
}

__global__ void ts_kernel(float* __restrict__ ts, int N, const int* __restrict__ dtp)
{
    int i = blockIdx.x * blockDim.x + threadIdx.x;
    if (i >= N) return;
    float dtf = 1.0f;
    if (dtp != nullptr) {
        int v = dtp[0];
        if (v >= 1 && v <= 1000000) dtf = (float)v;
        else { float f = __int_as_float(v); if (f > 0.0f && f < 1.0e6f) dtf = f; }
    }
    ts[i] = (float)i * dtf;
}

// ---------------------------------------------------------------------------
extern "C" void kernel_launch(void* const* d_in, const int* in_sizes, int n_in,
                              void* d_out, int out_size)
{
    const float* x0   = (const float*)d_in[0];
    const float* e0   = (const float*)d_in[1];
    const float* e1   = (const float*)d_in[2];
    const float* e2   = (const float*)d_in[3];
    const float* spd  = (const float*)d_in[4];
    const float* pan  = (const float*)d_in[5];
    const float* nan_ = (const float*)d_in[6];

    const int B = in_sizes[0] / 3;
    const int N = (int)((long long)in_sizes[4] / B);

    float* out    = (float*)d_out;
    float* ts     = out;
    float* X      = out + N;
    float* states = X + (size_t)3 * B * N;
    float* sp_o   = states + (size_t)B * N;
    float* pa_o   = sp_o   + (size_t)B * N;
    float* na_o   = pa_o   + (size_t)B * N;

    const int* dtp = (n_in > 8) ? (const int*)d_in[8] : nullptr;

    const bool fast = (N % LCH == 0) && (N / LCH == 32) && (B % 2 == 0) &&
                      ((long long)B * (N / LCH) <= (long long)MAXBC);

    if (fast) {
        const int C  = N / LCH;       // 32
        const int BC = B * C;
        chunk_kernel<<<(BC + 255) / 256, 256>>>(spd, pan, nan_, B, N, C);
        int nmax = (B > N) ? B : N;
        scan_kernel<<<(nmax + 255) / 256, 256>>>(x0, e0, e1, e2, ts, dtp, B, N, C);
        emit_kernel<<<B / 2, 64>>>(spd, pan, nan_, X, sp_o, pa_o, na_o,
                                   states, B, N, C);
    } else {
        const size_t bn_bytes = (size_t)B * N * sizeof(float);
        explorer_kernel<<<(B + PPB - 1) / PPB, PPB>>>(x0, e0, e1, e2,
                                                      spd, pan, nan_, X, B, N);
        ts_kernel<<<(N + 255) / 256, 256>>>(ts, N, dtp);
        cudaMemsetAsync(states, 0, bn_bytes, 0);
        cudaMemcpyAsync(sp_o, d_in[4], bn_bytes, cudaMemcpyDeviceToDevice, 0);
        cudaMemcpyAsync(pa_o, d_in[5], bn_bytes, cudaMemcpyDeviceToDevice, 0);
        cudaMemcpyAsync(na_o, d_in[6], bn_bytes, cudaMemcpyDeviceToDevice, 0);
    }

    (void)out_size; (void)n_in;
}

// round 5
// speedup vs baseline: 1.8493x; 1.8493x over previous
#include <cuda_runtime.h>
#include <cstdint>

// ---------------------------------------------------------------------------
// ParticleExplorer — fully fused time-parallel kernel.
// Per step: E <- E * Rz(pa) * Ry(na);  x <- x + sp * E.col0
// One warp per particle, one lane per 32-step chunk (N = 32*32 = 1024):
//   pass 1: lane computes its chunk transform (P, d) from identity
//   scan  : 5-step shfl inclusive scan (affine composition), -> exclusive
//   glue  : compose with particle initial (E0, x0), Gram-Schmidt renorm
//   pass 2: replay chunk from known start frame; emit X (float4, coalesced
//           per-lane contiguous), plus speeds/pa/na pass-through and states=0.
// Output: ts[N] | X[B][N][3] | states[B][N]=0 | speeds | pa | na
// ---------------------------------------------------------------------------

#define LCH 32   // steps per chunk == lanes per warp
#define WPB 8    // warps (particles) per block
#define THREADS (WPB * 32)

__device__ __forceinline__ void frame_step(float pa, float na,
    float& a0, float& a1, float& a2,
    float& b0, float& b1, float& b2,
    float& c0, float& c1, float& c2)
{
    float s1, cc1, s2, cc2;
    __sincosf(pa, &s1, &cc1);
    __sincosf(na, &s2, &cc2);
    float p00 = cc1 * cc2, p10 = s1 * cc2;
    float p02 = cc1 * s2,  p12 = s1 * s2;

    float na0 = fmaf(p00, a0, fmaf(p10, b0, -s2 * c0));
    float na1 = fmaf(p00, a1, fmaf(p10, b1, -s2 * c1));
    float na2 = fmaf(p00, a2, fmaf(p10, b2, -s2 * c2));
    float nb0 = fmaf(cc1, b0, -s1 * a0);
    float nb1 = fmaf(cc1, b1, -s1 * a1);
    float nb2 = fmaf(cc1, b2, -s1 * a2);
    float nc0 = fmaf(p02, a0, fmaf(p12, b0, cc2 * c0));
    float nc1 = fmaf(p02, a1, fmaf(p12, b1, cc2 * c1));
    float nc2 = fmaf(p02, a2, fmaf(p12, b2, cc2 * c2));
    a0 = na0; a1 = na1; a2 = na2;
    b0 = nb0; b1 = nb1; b2 = nb2;
    c0 = nc0; c1 = nc1; c2 = nc2;
}

// Affine chunk transform: v[0..8] = P columns (coeffs in chunk-start basis:
// newA = p0*a+p1*b+p2*c, newB = p3..p5, newC = p6..p8), v[9..11] = d.
// comb(earlier r, later q): apply r, then q.
__device__ __forceinline__ void compose(const float* __restrict__ r,
                                        const float* __restrict__ q,
                                        float* __restrict__ o)
{
    #pragma unroll
    for (int col = 0; col < 3; col++) {
        float q0 = q[col*3+0], q1 = q[col*3+1], q2 = q[col*3+2];
        o[col*3+0] = fmaf(q0, r[0], fmaf(q1, r[3], q2 * r[6]));
        o[col*3+1] = fmaf(q0, r[1], fmaf(q1, r[4], q2 * r[7]));
        o[col*3+2] = fmaf(q0, r[2], fmaf(q1, r[5], q2 * r[8]));
    }
    float d0 = q[9], d1 = q[10], d2 = q[11];
    o[9]  = fmaf(d0, r[0], fmaf(d1, r[3], fmaf(d2, r[6], r[9])));
    o[10] = fmaf(d0, r[1], fmaf(d1, r[4], fmaf(d2, r[7], r[10])));
    o[11] = fmaf(d0, r[2], fmaf(d1, r[5], fmaf(d2, r[8], r[11])));
}

__global__ void __launch_bounds__(THREADS)
fused_kernel(const float* __restrict__ x0, const float* __restrict__ e0i,
             const float* __restrict__ e1i, const float* __restrict__ e2i,
             const float* __restrict__ spd, const float* __restrict__ pan,
             const float* __restrict__ nanp,
             float* __restrict__ ts, float* __restrict__ X,
             float* __restrict__ states, float* __restrict__ spo,
             float* __restrict__ pao, float* __restrict__ nao,
             const int* __restrict__ dtp, int B, int N)
{
    const int tid  = threadIdx.x;
    const int lane = tid & 31;           // chunk index
    const int w    = tid >> 5;           // warp == particle slot
    const int p    = blockIdx.x * WPB + w;
    const int gtid = blockIdx.x * THREADS + tid;

    // ts (folded in; first N threads of the grid)
    if (gtid < N) {
        float dtf = 1.0f;
        if (dtp) {
            int v = dtp[0];
            if (v >= 1 && v <= 1000000) dtf = (float)v;
            else { float f = __int_as_float(v); if (f > 0.f && f < 1.0e6f) dtf = f; }
        }
        ts[gtid] = (float)gtid * dtf;
    }
    if (p >= B) return;

    const size_t base = (size_t)p * N + (size_t)lane * LCH;
    const float4* sp4 = (const float4*)(spd  + base);
    const float4* pa4 = (const float4*)(pan  + base);
    const float4* na4 = (const float4*)(nanp + base);

    // ---- Pass 1: chunk transform from identity --------------------------------
    float a0=1.f,a1=0.f,a2=0.f, b0=0.f,b1=1.f,b2=0.f, c0=0.f,c1=0.f,c2=1.f;
    float d0=0.f,d1=0.f,d2=0.f;
    #pragma unroll
    for (int q = 0; q < LCH / 4; q++) {
        float4 sp = sp4[q], pa = pa4[q], na = na4[q];
        frame_step(pa.x, na.x, a0,a1,a2,b0,b1,b2,c0,c1,c2);
        d0 = fmaf(sp.x,a0,d0); d1 = fmaf(sp.x,a1,d1); d2 = fmaf(sp.x,a2,d2);
        frame_step(pa.y, na.y, a0,a1,a2,b0,b1,b2,c0,c1,c2);
        d0 = fmaf(sp.y,a0,d0); d1 = fmaf(sp.y,a1,d1); d2 = fmaf(sp.y,a2,d2);
        frame_step(pa.z, na.z, a0,a1,a2,b0,b1,b2,c0,c1,c2);
        d0 = fmaf(sp.z,a0,d0); d1 = fmaf(sp.z,a1,d1); d2 = fmaf(sp.z,a2,d2);
        frame_step(pa.w, na.w, a0,a1,a2,b0,b1,b2,c0,c1,c2);
        d0 = fmaf(sp.w,a0,d0); d1 = fmaf(sp.w,a1,d1); d2 = fmaf(sp.w,a2,d2);
    }

    float v[12] = {a0,a1,a2, b0,b1,b2, c0,c1,c2, d0,d1,d2};

    // ---- Warp inclusive scan (Hillis-Steele, affine composition) --------------
    #pragma unroll
    for (int off = 1; off <= 16; off <<= 1) {
        float o[12];
        #pragma unroll
        for (int i = 0; i < 12; i++)
            o[i] = __shfl_up_sync(0xffffffffu, v[i], off);
        if (lane >= off) {
            float t[12];
            compose(o, v, t);
            #pragma unroll
            for (int i = 0; i < 12; i++) v[i] = t[i];
        }
    }
    // exclusive prefix
    float e[12];
    #pragma unroll
    for (int i = 0; i < 12; i++)
        e[i] = __shfl_up_sync(0xffffffffu, v[i], 1);
    if (lane == 0) {
        e[0]=1.f; e[1]=0.f; e[2]=0.f;
        e[3]=0.f; e[4]=1.f; e[5]=0.f;
        e[6]=0.f; e[7]=0.f; e[8]=1.f;
        e[9]=0.f; e[10]=0.f; e[11]=0.f;
    }

    // ---- Compose with particle initial frame/pos -------------------------------
    float A0=e0i[p*3+0], A1=e0i[p*3+1], A2=e0i[p*3+2];
    float B0=e1i[p*3+0], B1=e1i[p*3+1], B2=e1i[p*3+2];
    float C0=e2i[p*3+0], C1=e2i[p*3+1], C2=e2i[p*3+2];
    float x =x0 [p*3+0], y =x0 [p*3+1], z =x0 [p*3+2];

    a0 = fmaf(e[0],A0, fmaf(e[1],B0, e[2]*C0));
    a1 = fmaf(e[0],A1, fmaf(e[1],B1, e[2]*C1));
    a2 = fmaf(e[0],A2, fmaf(e[1],B2, e[2]*C2));
    b0 = fmaf(e[3],A0, fmaf(e[4],B0, e[5]*C0));
    b1 = fmaf(e[3],A1, fmaf(e[4],B1, e[5]*C1));
    b2 = fmaf(e[3],A2, fmaf(e[4],B2, e[5]*C2));
    c0 = fmaf(e[6],A0, fmaf(e[7],B0, e[8]*C0));
    c1 = fmaf(e[6],A1, fmaf(e[7],B1, e[8]*C1));
    c2 = fmaf(e[6],A2, fmaf(e[7],B2, e[8]*C2));
    x  = fmaf(e[9],A0, fmaf(e[10],B0, fmaf(e[11],C0, x)));
    y  = fmaf(e[9],A1, fmaf(e[10],B1, fmaf(e[11],C1, y)));
    z  = fmaf(e[9],A2, fmaf(e[10],B2, fmaf(e[11],C2, z)));

    // Gram-Schmidt renorm of the chunk-start frame (kills composition drift).
    {
        float inv = rsqrtf(fmaf(a0,a0, fmaf(a1,a1, a2*a2)));
        a0*=inv; a1*=inv; a2*=inv;
        float dd = fmaf(b0,a0, fmaf(b1,a1, b2*a2));
        b0 = fmaf(-dd,a0,b0); b1 = fmaf(-dd,a1,b1); b2 = fmaf(-dd,a2,b2);
        inv = rsqrtf(fmaf(b0,b0, fmaf(b1,b1, b2*b2)));
        b0*=inv; b1*=inv; b2*=inv;
        c0 = a1*b2 - a2*b1;
        c1 = a2*b0 - a0*b2;
        c2 = a0*b1 - a1*b0;
    }

    // ---- Pass 2: replay chunk, emit everything ---------------------------------
    float4* spo4 = (float4*)(spo    + base);
    float4* pao4 = (float4*)(pao    + base);
    float4* nao4 = (float4*)(nao    + base);
    float4* st4  = (float4*)(states + base);
    float4* X4   = (float4*)(X + (size_t)p * 3 * N + (size_t)lane * (3 * LCH));
    const float4 zero4 = make_float4(0.f, 0.f, 0.f, 0.f);

    #pragma unroll
    for (int q = 0; q < LCH / 4; q++) {
        float4 sp = sp4[q], pa = pa4[q], na = na4[q];
        spo4[q] = sp; pao4[q] = pa; nao4[q] = na; st4[q] = zero4;

        float4 o0, o1, o2;
        frame_step(pa.x, na.x, a0,a1,a2,b0,b1,b2,c0,c1,c2);
        x = fmaf(sp.x,a0,x); y = fmaf(sp.x,a1,y); z = fmaf(sp.x,a2,z);
        o0.x = x; o0.y = y; o0.z = z;
        frame_step(pa.y, na.y, a0,a1,a2,b0,b1,b2,c0,c1,c2);
        x = fmaf(sp.y,a0,x); y = fmaf(sp.y,a1,y); z = fmaf(sp.y,a2,z);
        o0.w = x; o1.x = y; o1.y = z;
        frame_step(pa.z, na.z, a0,a1,a2,b0,b1,b2,c0,c1,c2);
        x = fmaf(sp.z,a0,x); y = fmaf(sp.z,a1,y); z = fmaf(sp.z,a2,z);
        o1.z = x; o1.w = y; o2.x = z;
        frame_step(pa.w, na.w, a0,a1,a2,b0,b1,b2,c0,c1,c2);
        x = fmaf(sp.w,a0,x); y = fmaf(sp.w,a1,y); z = fmaf(sp.w,a2,z);
        o2.y = x; o2.z = y; o2.w = z;

        X4[q*3 + 0] = o0;
        X4[q*3 + 1] = o1;
        X4[q*3 + 2] = o2;
    }
}

// ---------------------------------------------------------------------------
// Fallback (proven round-2 path) for unexpected shapes.
// ---------------------------------------------------------------------------
#define PPB 32
#define TT  32
#define SPITCH 33

__global__ void __launch_bounds__(PPB)
explorer_kernel(const float* __restrict__ x0, const float* __restrict__ e0i,
                const float* __restrict__ e1i, const float* __restrict__ e2i,
                const float* __restrict__ spd, const float* __restrict__ pan,
                const float* __restrict__ nan_, float* __restrict__ X,
                int B, int N)
{
    __shared__ float s_sp[TT][SPITCH];
    __shared__ float s_pa[TT][SPITCH];
    __shared__ float s_na[TT][SPITCH];
    __shared__ float s_X[3 * TT][SPITCH];

    const int lane  = threadIdx.x;
    const int pbase = blockIdx.x * PPB;
    const int p     = pbase + lane;
    const bool act  = (p < B);

    float a0=1.f,a1=0.f,a2=0.f, b0=0.f,b1=1.f,b2=0.f, c0=0.f,c1=0.f,c2=1.f;
    float x=0.f, y=0.f, z=0.f;
    if (act) {
        a0=e0i[p*3+0]; a1=e0i[p*3+1]; a2=e0i[p*3+2];
        b0=e1i[p*3+0]; b1=e1i[p*3+1]; b2=e1i[p*3+2];
        c0=e2i[p*3+0]; c1=e2i[p*3+1]; c2=e2i[p*3+2];
        x =x0 [p*3+0]; y =x0 [p*3+1]; z =x0 [p*3+2];
    }

    for (int t0 = 0; t0 < N; t0 += TT) {
        #pragma unroll
        for (int k = 0; k < PPB; k++) {
            int gp = pbase + k;
            float vs=0.f, vp=0.f, vn=0.f;
            if (gp < B && t0 + lane < N) {
                size_t gidx = (size_t)gp * N + (size_t)t0 + lane;
                vs = spd[gidx]; vp = pan[gidx]; vn = nan_[gidx];
            }
            s_sp[lane][k]=vs; s_pa[lane][k]=vp; s_na[lane][k]=vn;
        }
        __syncthreads();

        if (act) {
            int nt = (N - t0 < TT) ? (N - t0) : TT;
            for (int tt = 0; tt < nt; tt++) {
                frame_step(s_pa[tt][lane], s_na[tt][lane],
                           a0,a1,a2,b0,b1,b2,c0,c1,c2);
                float s = s_sp[tt][lane];
                x = fmaf(s,a0,x); y = fmaf(s,a1,y); z = fmaf(s,a2,z);
                s_X[3*tt+0][lane]=x; s_X[3*tt+1][lane]=y; s_X[3*tt+2][lane]=z;
            }
            float inv = rsqrtf(fmaf(a0,a0, fmaf(a1,a1, a2*a2)));
            a0*=inv; a1*=inv; a2*=inv;
            float d = fmaf(b0,a0, fmaf(b1,a1, b2*a2));
            b0=fmaf(-d,a0,b0); b1=fmaf(-d,a1,b1); b2=fmaf(-d,a2,b2);
            inv = rsqrtf(fmaf(b0,b0, fmaf(b1,b1, b2*b2)));
            b0*=inv; b1*=inv; b2*=inv;
            c0=a1*b2-a2*b1; c1=a2*b0-a0*b2; c2=a0*b1-a1*b0;
        }
        __syncthreads();

        #pragma unroll
        for (int k = 0; k < PPB; k++) {
            int gp = pbase + k;
            if (gp < B) {
                size_t bidx = (size_t)gp*3*N + (size_t)t0*3;
                #pragma unroll
                for (int chn = 0; chn < 3; chn++)
                    if (t0*3 + chn*32 + lane < 3*N)
                        X[bidx + chn*32 + lane] = s_X[chn*32 + lane][k];
            }
        }
    }
}

__global__ void ts_kernel(float* __restrict__ ts, int N, const int* __restrict__ dtp)
{
    int i = blockIdx.x * blockDim.x + threadIdx.x;
    if (i >= N) return;
    float dtf = 1.0f;
    if (dtp != nullptr) {
        int v = dtp[0];
        if (v >= 1 && v <= 1000000) dtf = (float)v;
        else { float f = __int_as_float(v); if (f > 0.0f && f < 1.0e6f) dtf = f; }
    }
    ts[i] = (float)i * dtf;
}

// ---------------------------------------------------------------------------
extern "C" void kernel_launch(void* const* d_in, const int* in_sizes, int n_in,
                              void* d_out, int out_size)
{
    const float* x0   = (const float*)d_in[0];
    const float* e0   = (const float*)d_in[1];
    const float* e1   = (const float*)d_in[2];
    const float* e2   = (const float*)d_in[3];
    const float* spd  = (const float*)d_in[4];
    const float* pan  = (const float*)d_in[5];
    const float* nan_ = (const float*)d_in[6];

    const int B = in_sizes[0] / 3;
    const int N = (int)((long long)in_sizes[4] / B);

    float* out    = (float*)d_out;
    float* ts     = out;
    float* X      = out + N;
    float* states = X + (size_t)3 * B * N;
    float* sp_o   = states + (size_t)B * N;
    float* pa_o   = sp_o   + (size_t)B * N;
    float* na_o   = pa_o   + (size_t)B * N;

    const int* dtp = (n_in > 8) ? (const int*)d_in[8] : nullptr;

    const bool fast = (N == LCH * 32) && (B % WPB == 0) &&
                      ((size_t)B * 32 * THREADS > 0);

    if (fast) {
        fused_kernel<<<B / WPB, THREADS>>>(x0, e0, e1, e2, spd, pan, nan_,
                                           ts, X, states, sp_o, pa_o, na_o,
                                           dtp, B, N);
    } else {
        const size_t bn_bytes = (size_t)B * N * sizeof(float);
        explorer_kernel<<<(B + PPB - 1) / PPB, PPB>>>(x0, e0, e1, e2,
                                                      spd, pan, nan_, X, B, N);
        ts_kernel<<<(N + 255) / 256, 256>>>(ts, N, dtp);
        cudaMemsetAsync(states, 0, bn_bytes, 0);
        cudaMemcpyAsync(sp_o, d_in[4], bn_bytes, cudaMemcpyDeviceToDevice, 0);
        cudaMemcpyAsync(pa_o, d_in[5], bn_bytes, cudaMemcpyDeviceToDevice, 0);
        cudaMemcpyAsync(na_o, d_in[6], bn_bytes, cudaMemcpyDeviceToDevice, 0);
    }

    (void)out_size; (void)n_in;
}